// round 13
// baseline (speedup 1.0000x reference)
#include <cuda_runtime.h>
#include <cuda_bf16.h>
#include <mma.h>
#include <cstdint>
using namespace nvcuda;

// Problem constants
#define NN   4096
#define NB   512
#define NP   4224          // 4096 + 128 pad rows (row 4096 = Z for zdot)
#define DTC  0.1f

// GEMM tiling
#define BM 128
#define BN 128
#define BK 32
#define NCHUNK (NN / BK)   // 128
#define STAGES 3
#define NT 512             // threads per CTA (16 warps, 4x4 warp grid)

// smem strides (elems) and layout (bytes)
#define A_STR 40
#define B_STR 136
#define A_BYTES (BM * A_STR * 2)              // 10240
#define B_BYTES (BK * B_STR * 2)              // 8704
#define ST_AH 0
#define ST_AL A_BYTES
#define ST_BH (2 * A_BYTES)
#define ST_BL (2 * A_BYTES + B_BYTES)
#define STAGE_BYTES (2 * A_BYTES + 2 * B_BYTES)   // 37888
#define SMEM_DYN (STAGES * STAGE_BYTES)           // 113664
#define C_STR 132                                 // epilogue fp32 tile stride

// ------------------------- device scratch (no allocs) -----------------------
__device__ __align__(256) __nv_bfloat16 g_Whi[(size_t)NP * NN];
__device__ __align__(256) __nv_bfloat16 g_Wlo[(size_t)NP * NN];
__device__ __align__(256) __nv_bfloat16 g_hhi[2][(size_t)NN * NB];  // [i][b]
__device__ __align__(256) __nv_bfloat16 g_hlo[2][(size_t)NN * NB];
__device__ __align__(256) float g_dump[(size_t)NN * NB];
__device__ float g_x[2][2 * NB];
__device__ float g_q[2][NB];

__device__ __forceinline__ void cpasync16(uint32_t dst, const void* src) {
    asm volatile("cp.async.cg.shared.global [%0], [%1], 16;\n" :: "r"(dst), "l"(src));
}
#define CP_COMMIT() asm volatile("cp.async.commit_group;\n" ::: "memory")
#define CP_WAIT(n)  asm volatile("cp.async.wait_group %0;\n" :: "n"(n) : "memory")

// ---------------------------------------------------------------------------
// prep: W_eff hi/lo split; padded rows (row 4096 = Z, rest 0)
// ---------------------------------------------------------------------------
__global__ void prep_W(const float* __restrict__ Wr, const float* __restrict__ U,
                       const float* __restrict__ V, const float* __restrict__ M,
                       const float* __restrict__ Z, const float* __restrict__ C,
                       const float* __restrict__ Bm) {
    int j = blockIdx.x * 256 + threadIdx.x;
    int i = blockIdx.y;
    size_t idx = (size_t)i * NN + j;
    float w;
    if (i < NN) {
        float cb = C[0] * Bm[0] + C[1] * Bm[1];
        float uv = 0.f;
#pragma unroll
        for (int r = 0; r < 4; r++) uv += U[i * 4 + r] * V[j * 4 + r];
        w = DTC * Wr[idx] + DTC * uv + M[i] * cb * Z[j];
        if (i == j) w += 1.0f - DTC;
    } else if (i == NN) {
        w = Z[j];
    } else {
        w = 0.f;
    }
    __nv_bfloat16 hi = __float2bfloat16(w);
    g_Whi[idx] = hi;
    g_Wlo[idx] = __float2bfloat16(w - __bfloat162float(hi));
}

// x_0 = [x0;x1]; q_0 = DT*(C@A)@x_0 ; traj[0] x rows
__global__ void init_x(const float* __restrict__ x0, const float* __restrict__ x1,
                       const float* __restrict__ A, const float* __restrict__ C,
                       float* __restrict__ xDst0) {
    int b = blockIdx.x * 256 + threadIdx.x;
    if (b >= NB) return;
    float v0 = x0[b], v1 = x1[b];
    g_x[0][b] = v0;
    g_x[0][NB + b] = v1;
    xDst0[b] = v0;
    xDst0[NB + b] = v1;
    float CA0 = C[0] * A[0] + C[1] * A[2];
    float CA1 = C[0] * A[1] + C[1] * A[3];
    g_q[0][b] = DTC * (CA0 * v0 + CA1 * v1);
}

// split h0 -> bf16 hi/lo buffer 0
__global__ void hsplit(const float* __restrict__ h0) {
    size_t idx = (size_t)blockIdx.x * 256 + threadIdx.x;
    float v = h0[idx];
    __nv_bfloat16 hi = __float2bfloat16(v);
    g_hhi[0][idx] = hi;
    g_hlo[0][idx] = __float2bfloat16(v - __bfloat162float(hi));
}

// ---------------------------------------------------------------------------
// Fused pipelined wmma GEMM step (512 threads, 16 warps, 4x4 warp grid):
//   acc[4224,512] = Whi@hhi + Whi@hlo + Wlo@hhi  (fp32)
//   rows<4096: v = acc + M[i]*q[b] -> traj[t+1] fp32 + hhi/hlo bf16
//   row 4096 tile (blockIdx.y==32): zdot -> con_t, x_{t+1}, q_{t+1}
// ---------------------------------------------------------------------------
__device__ __forceinline__ void load_stage(uint32_t sb, int tid, int kc, int stage,
        int rowBase, int colBase,
        const __nv_bfloat16* __restrict__ Bh, const __nv_bfloat16* __restrict__ Bl) {
    uint32_t base = sb + stage * STAGE_BYTES;
    int k0 = kc * BK;
    // A hi/lo: 128x32 bf16 = 512 16B-chunks each; 1 per thread
    {
        int r = tid >> 2, c4 = tid & 3;
        uint32_t so = (uint32_t)(r * A_STR + c4 * 8) * 2;
        size_t go = (size_t)(rowBase + r) * NN + k0 + c4 * 8;
        cpasync16(base + ST_AH + so, g_Whi + go);
        cpasync16(base + ST_AL + so, g_Wlo + go);
    }
    // B hi/lo: 32x128 bf16 = 512 chunks each; 1 per thread
    {
        int kr = tid >> 4, cc = tid & 15;
        uint32_t so = (uint32_t)(kr * B_STR + cc * 8) * 2;
        size_t go = (size_t)(k0 + kr) * NB + colBase + cc * 8;
        cpasync16(base + ST_BH + so, Bh + go);
        cpasync16(base + ST_BL + so, Bl + go);
    }
    CP_COMMIT();
}

__global__ __launch_bounds__(NT, 1) void gemm_step(
    const __nv_bfloat16* __restrict__ Bh, const __nv_bfloat16* __restrict__ Bl,
    __nv_bfloat16* __restrict__ hhN, __nv_bfloat16* __restrict__ hlN,
    float* __restrict__ trajH, float* __restrict__ xDst,
    float* __restrict__ conDst, const float* __restrict__ Mv,
    const float* __restrict__ A, const float* __restrict__ Bm,
    const float* __restrict__ C, int cur, int nxt) {
    extern __shared__ __align__(128) char smem[];
    const int tid = threadIdx.x;
    const int wid = tid >> 5;
    const int wm = wid >> 2;          // 0..3: 32-row band
    const int wn = wid & 3;           // 0..3: 32-col band
    const int colBase = blockIdx.x * BN;
    const int rowBase = blockIdx.y * BM;
    const bool zTile = (rowBase >= NN);
    uint32_t sb = (uint32_t)__cvta_generic_to_shared(smem);

    wmma::fragment<wmma::accumulator, 16, 16, 16, float> acc[2][2];
#pragma unroll
    for (int i = 0; i < 2; i++)
#pragma unroll
        for (int j = 0; j < 2; j++) wmma::fill_fragment(acc[i][j], 0.f);

    load_stage(sb, tid, 0, 0, rowBase, colBase, Bh, Bl);
    load_stage(sb, tid, 1, 1, rowBase, colBase, Bh, Bl);

    for (int c = 0; c < NCHUNK; c++) {
        if (c + 1 < NCHUNK) { CP_WAIT(1); } else { CP_WAIT(0); }
        __syncthreads();
        if (c + 2 < NCHUNK)
            load_stage(sb, tid, c + 2, (c + 2) % STAGES, rowBase, colBase, Bh, Bl);

        char* st = smem + (c % STAGES) * STAGE_BYTES;
        __nv_bfloat16* Ahs = (__nv_bfloat16*)(st + ST_AH);
        __nv_bfloat16* Als = (__nv_bfloat16*)(st + ST_AL);
        __nv_bfloat16* Bhs = (__nv_bfloat16*)(st + ST_BH);
        __nv_bfloat16* Bls = (__nv_bfloat16*)(st + ST_BL);

#pragma unroll
        for (int kk = 0; kk < BK; kk += 16) {
            wmma::fragment<wmma::matrix_a, 16, 16, 16, __nv_bfloat16, wmma::row_major> ah[2], al[2];
#pragma unroll
            for (int i = 0; i < 2; i++) {
                wmma::load_matrix_sync(ah[i], Ahs + (wm * 32 + i * 16) * A_STR + kk, A_STR);
                wmma::load_matrix_sync(al[i], Als + (wm * 32 + i * 16) * A_STR + kk, A_STR);
            }
#pragma unroll
            for (int j = 0; j < 2; j++) {
                wmma::fragment<wmma::matrix_b, 16, 16, 16, __nv_bfloat16, wmma::row_major> bh, bl;
                wmma::load_matrix_sync(bh, Bhs + kk * B_STR + wn * 32 + j * 16, B_STR);
                wmma::load_matrix_sync(bl, Bls + kk * B_STR + wn * 32 + j * 16, B_STR);
#pragma unroll
                for (int i = 0; i < 2; i++) {
                    wmma::mma_sync(acc[i][j], ah[i], bh, acc[i][j]);
                    wmma::mma_sync(acc[i][j], ah[i], bl, acc[i][j]);
                    wmma::mma_sync(acc[i][j], al[i], bh, acc[i][j]);
                }
            }
        }
        __syncthreads();
    }

    // ------------------------------ epilogue --------------------------------
    float* sacc = (float*)smem;   // 128 x C_STR fp32 = 67584 B (pipeline dead)
#pragma unroll
    for (int i = 0; i < 2; i++)
#pragma unroll
        for (int j = 0; j < 2; j++)
            wmma::store_matrix_sync(sacc + (wm * 32 + i * 16) * C_STR + wn * 32 + j * 16,
                                    acc[i][j], C_STR, wmma::mem_row_major);
    __syncthreads();

    if (zTile) {
        // row 0 of this tile = global row 4096 = Z @ h_t = zdot
        if (tid < BN) {
            int b = colBase + tid;
            float zd = sacc[tid];
            conDst[b] = Bm[1] * zd;
            float x0c = g_x[cur][b];
            float x1c = g_x[cur][NB + b];
            float nx0 = A[0] * x0c + A[1] * x1c + Bm[0] * zd;
            float nx1 = A[2] * x0c + A[3] * x1c + Bm[1] * zd;
            g_x[nxt][b] = nx0;
            g_x[nxt][NB + b] = nx1;
            xDst[b] = nx0;
            xDst[NB + b] = nx1;
            float CA0 = C[0] * A[0] + C[1] * A[2];
            float CA1 = C[0] * A[1] + C[1] * A[3];
            g_q[nxt][b] = DTC * (CA0 * nx0 + CA1 * nx1);
        }
    } else {
        for (int e = tid; e < BM * BN; e += NT) {
            int i = e >> 7;         // 0..127
            int b = e & 127;
            float v = sacc[i * C_STR + b] + Mv[rowBase + i] * g_q[cur][colBase + b];
            size_t o = (size_t)(rowBase + i) * NB + colBase + b;
            trajH[o] = v;
            __nv_bfloat16 hi = __float2bfloat16(v);
            hhN[o] = hi;
            hlN[o] = __float2bfloat16(v - __bfloat162float(hi));
        }
    }
}

// ---------------------------------------------------------------------------
extern "C" void kernel_launch(void* const* d_in, const int* in_sizes, int n_in,
                              void* d_out, int out_size) {
    const float* x0 = (const float*)d_in[0];
    const float* x1 = (const float*)d_in[1];
    const float* h0 = (const float*)d_in[2];
    const float* A  = (const float*)d_in[3];
    const float* Bm = (const float*)d_in[4];
    const float* C  = (const float*)d_in[5];
    const float* M  = (const float*)d_in[6];
    const float* Z  = (const float*)d_in[7];
    const float* U  = (const float*)d_in[8];
    const float* V  = (const float*)d_in[9];
    const float* Wr = (const float*)d_in[10];
    float* out = (float*)d_out;

    int steps = out_size / ((NN + 2 + 1) * NB);
    if (steps <= 0) steps = 64;

    cudaFuncSetAttribute(gemm_step, cudaFuncAttributeMaxDynamicSharedMemorySize, SMEM_DYN);

    __nv_bfloat16* hh = nullptr;
    __nv_bfloat16* hl = nullptr;
    float* dump = nullptr;
    cudaGetSymbolAddress((void**)&hh, g_hhi);
    cudaGetSymbolAddress((void**)&hl, g_hlo);
    cudaGetSymbolAddress((void**)&dump, g_dump);

    const size_t trajStride = (size_t)(NN + 2) * NB;
    float* conBase = out + (size_t)steps * trajStride;
    const size_t hbuf = (size_t)NN * NB;

    // one-time prep
    prep_W<<<dim3(NN / 256, NP), 256>>>(Wr, U, V, M, Z, C, Bm);
    init_x<<<2, 256>>>(x0, x1, A, C, out);
    hsplit<<<NN * NB / 256, 256>>>(h0);
    cudaMemcpyAsync(out + 2 * NB, h0, hbuf * sizeof(float),
                    cudaMemcpyDeviceToDevice, 0);

    for (int t = 0; t < steps; t++) {
        int cur = t & 1;
        int nxt = cur ^ 1;
        bool last = (t + 1 >= steps);
        float* trajNext = last ? dump : out + (size_t)(t + 1) * trajStride + 2 * NB;
        float* xNext    = last ? dump : out + (size_t)(t + 1) * trajStride;

        gemm_step<<<dim3(NB / BN, NP / BM), NT, SMEM_DYN>>>(
            hh + cur * hbuf, hl + cur * hbuf,
            hh + nxt * hbuf, hl + nxt * hbuf,
            trajNext, xNext, conBase + (size_t)t * NB,
            M, A, Bm, C, cur, nxt);
    }
}